// round 1
// baseline (speedup 1.0000x reference)
#include <cuda_runtime.h>
#include <stdint.h>

#define RES 512
#define CH 32
#define PLANE_ELEMS (RES * RES * CH)

// (H, W, C) transposed planes: each texel = 32 contiguous floats = one 128B line.
__device__ __align__(16) float g_TT[3][PLANE_ELEMS];

// ---------------------------------------------------------------------------
// Transpose (C, H, W) -> (H, W, C) via shared-memory 32x32 tile.
// grid = (RES, RES/32, 3), block = (32, 32)
// ---------------------------------------------------------------------------
__global__ __launch_bounds__(1024) void triplane_transpose_kernel(
    const float* __restrict__ t_xy,
    const float* __restrict__ t_yz,
    const float* __restrict__ t_zx)
{
    __shared__ float tile[32][33];

    const int y  = blockIdx.x;        // row in H
    const int x0 = blockIdx.y * 32;   // tile base in W
    const int p  = blockIdx.z;        // plane
    const int tx = threadIdx.x;
    const int ty = threadIdx.y;

    const float* src = (p == 0) ? t_xy : (p == 1) ? t_yz : t_zx;

    // read: channel = ty (fixed per row), x = x0 + tx -> coalesced 128B rows
    tile[ty][tx] = src[ty * (RES * RES) + y * RES + x0 + tx];
    __syncthreads();

    // write: x = x0 + ty, c = tx -> dst contiguous in tx (coalesced 128B rows)
    g_TT[p][(y * RES + x0 + ty) * CH + tx] = tile[tx][ty];
}

// ---------------------------------------------------------------------------
// Sampling kernel: 8 lanes per point, each lane owns 4 channels (float4).
// A warp covers 4 points; every corner fetch is one 128B-aligned cache line.
// ---------------------------------------------------------------------------
__global__ __launch_bounds__(256) void triplane_sample_kernel(
    const float* __restrict__ xyz,
    float* __restrict__ out,
    int npts)
{
    const int gtid = blockIdx.x * blockDim.x + threadIdx.x;
    const int pid  = gtid >> 3;       // point id
    const int c4   = gtid & 7;        // which float4 chunk of the 32 channels
    if (pid >= npts) return;

    const float cx = __ldg(xyz + pid * 3 + 0);
    const float cy = __ldg(xyz + pid * 3 + 1);
    const float cz = __ldg(xyz + pid * 3 + 2);

    // plane p: x-coord (W dim) = cA[p], y-coord (H dim) = cB[p]
    // f_xy: (X, Y)   f_yz: (Y, Z)   f_zx: (Z, X)
    const float cA[3] = {cx, cy, cz};
    const float cB[3] = {cy, cz, cx};

    float4 acc = make_float4(0.f, 0.f, 0.f, 0.f);

#pragma unroll
    for (int p = 0; p < 3; ++p) {
        // x = ((c + 1) * RES - 1) * 0.5 = 256*c + 255.5
        const float xf = fmaf(cA[p], 256.0f, 255.5f);
        const float yf = fmaf(cB[p], 256.0f, 255.5f);

        const float x0f = floorf(xf);
        const float y0f = floorf(yf);
        const float wx1 = xf - x0f;
        const float wy1 = yf - y0f;
        const float wx0 = 1.0f - wx1;
        const float wy0 = 1.0f - wy1;

        const int ix0 = (int)x0f;
        const int iy0 = (int)y0f;
        const int ix1 = ix0 + 1;
        const int iy1 = iy0 + 1;

        const bool vx0 = ((unsigned)ix0 < RES);
        const bool vx1 = ((unsigned)ix1 < RES);
        const bool vy0 = ((unsigned)iy0 < RES);
        const bool vy1 = ((unsigned)iy1 < RES);

        const float* base = g_TT[p] + c4 * 4;

        if (vy0 & vx0) {
            const float4 v = __ldg((const float4*)(base + (iy0 * RES + ix0) * CH));
            const float w = wy0 * wx0;
            acc.x = fmaf(w, v.x, acc.x); acc.y = fmaf(w, v.y, acc.y);
            acc.z = fmaf(w, v.z, acc.z); acc.w = fmaf(w, v.w, acc.w);
        }
        if (vy0 & vx1) {
            const float4 v = __ldg((const float4*)(base + (iy0 * RES + ix1) * CH));
            const float w = wy0 * wx1;
            acc.x = fmaf(w, v.x, acc.x); acc.y = fmaf(w, v.y, acc.y);
            acc.z = fmaf(w, v.z, acc.z); acc.w = fmaf(w, v.w, acc.w);
        }
        if (vy1 & vx0) {
            const float4 v = __ldg((const float4*)(base + (iy1 * RES + ix0) * CH));
            const float w = wy1 * wx0;
            acc.x = fmaf(w, v.x, acc.x); acc.y = fmaf(w, v.y, acc.y);
            acc.z = fmaf(w, v.z, acc.z); acc.w = fmaf(w, v.w, acc.w);
        }
        if (vy1 & vx1) {
            const float4 v = __ldg((const float4*)(base + (iy1 * RES + ix1) * CH));
            const float w = wy1 * wx1;
            acc.x = fmaf(w, v.x, acc.x); acc.y = fmaf(w, v.y, acc.y);
            acc.z = fmaf(w, v.z, acc.z); acc.w = fmaf(w, v.w, acc.w);
        }
    }

    // contiguous 512B per warp
    ((float4*)out)[pid * 8 + c4] = acc;
}

// ---------------------------------------------------------------------------
// kernel_launch
// inputs (metadata order): xyz [N*3], T_xy, T_yz, T_zx [1*32*512*512] fp32
// output: [N*32] fp32
// ---------------------------------------------------------------------------
extern "C" void kernel_launch(void* const* d_in, const int* in_sizes, int n_in,
                              void* d_out, int out_size)
{
    const float* xyz  = (const float*)d_in[0];
    const float* t_xy = (const float*)d_in[1];
    const float* t_yz = (const float*)d_in[2];
    const float* t_zx = (const float*)d_in[3];
    float* out = (float*)d_out;

    const int npts = in_sizes[0] / 3;

    // 1) transpose planes to (H, W, C)
    dim3 tgrid(RES, RES / 32, 3);
    dim3 tblock(32, 32);
    triplane_transpose_kernel<<<tgrid, tblock>>>(t_xy, t_yz, t_zx);

    // 2) sample: 8 threads per point
    const long long total = (long long)npts * 8;
    const int block = 256;
    const int grid = (int)((total + block - 1) / block);
    triplane_sample_kernel<<<grid, block>>>(xyz, out, npts);
}